// round 15
// baseline (speedup 1.0000x reference)
#include <cuda_runtime.h>
#include <cstdint>

#define NN 30000
#define DMAXX 16

// ---------------- scratch (static device arrays; no cudaMalloc) -------------
__device__ __align__(16) float d_G1[(size_t)NN * 512];
__device__ __align__(16) float d_GB[(size_t)NN * 1024];
__device__ __align__(16) float d_H1p[(size_t)NN * 128];
__device__ __align__(16) float d_C1p[(size_t)NN * 128];
__device__ __align__(16) float d_M1[(size_t)NN * 128];
__device__ __align__(16) float d_X1[(size_t)NN * 256];
__device__ __align__(16) float d_G2[(size_t)NN * 1024];
__device__ __align__(16) float d_H2p[(size_t)NN * 256];
__device__ __align__(16) float d_C2p[(size_t)NN * 256];
__device__ __align__(16) float d_M2[(size_t)NN * 256];
__device__ __align__(16) float d_Fr[(size_t)NN * 128];
__device__ __align__(16) float d_Wih1r[512 * 128];
__device__ __align__(16) float d_Whh1r[512 * 128];
__device__ __align__(16) float d_Wih2r[1024 * 256];
__device__ __align__(16) float d_Whh2r[1024 * 256];
__device__ __align__(16) float d_Wfc1[256 * 256];
__device__ __align__(16) float d_Wfc2[64 * 512];
__device__ int d_perm[NN];
__device__ int d_hist[17];
__device__ int d_suffix[18];
__device__ int d_offset[17];

// ---------------- tf32 round helpers ----------------------------------------
__device__ __forceinline__ uint32_t f2tf32(float x) {
    uint32_t y;
    asm("cvt.rna.tf32.f32 %0, %1;" : "=r"(y) : "f"(x));
    return y;
}
__device__ __forceinline__ float rtf(float x) { return __uint_as_float(f2tf32(x)); }
__device__ __forceinline__ float4 rtf4(float4 v) {
    v.x = rtf(v.x); v.y = rtf(v.y); v.z = rtf(v.z); v.w = rtf(v.w);
    return v;
}

#define R_FEAT 960000
#define R_WIH1 (R_FEAT + 16384)
#define R_WHH1 (R_WIH1 + 16384)
#define R_WIH2 (R_WHH1 + 65536)
#define R_WHH2 (R_WIH2 + 65536)
__global__ void k_round_all(const float* __restrict__ feat,
                            const float* __restrict__ wih1, const float* __restrict__ whh1,
                            const float* __restrict__ wih2, const float* __restrict__ whh2) {
    int i = blockIdx.x * blockDim.x + threadIdx.x;
    if (i < R_FEAT)      ((float4*)d_Fr)[i]    = rtf4(((const float4*)feat)[i]);
    else if (i < R_WIH1) ((float4*)d_Wih1r)[i - R_FEAT] = rtf4(((const float4*)wih1)[i - R_FEAT]);
    else if (i < R_WHH1) ((float4*)d_Whh1r)[i - R_WIH1] = rtf4(((const float4*)whh1)[i - R_WIH1]);
    else if (i < R_WIH2) ((float4*)d_Wih2r)[i - R_WHH1] = rtf4(((const float4*)wih2)[i - R_WHH1]);
    else if (i < R_WHH2) ((float4*)d_Whh2r)[i - R_WIH2] = rtf4(((const float4*)whh2)[i - R_WIH2]);
}

__global__ void k_pack2(const float* __restrict__ a, const float* __restrict__ b,
                        float* __restrict__ out, int rows, int k1, int k2) {
    int ktot = k1 + k2;
    int n4 = rows * ktot / 4;
    int i = blockIdx.x * blockDim.x + threadIdx.x;
    if (i >= n4) return;
    int r = i / (ktot / 4), c4 = (i % (ktot / 4)) * 4;
    float4 v = (c4 < k1) ? *(const float4*)&a[(size_t)r * k1 + c4]
                         : *(const float4*)&b[(size_t)r * k2 + (c4 - k1)];
    ((float4*)out)[i] = rtf4(v);
}

// ---------------- degree counting sort (descending) -------------------------
__global__ void k_hist_zero() { if (threadIdx.x < 17) d_hist[threadIdx.x] = 0; }
__global__ void k_hist(const int* __restrict__ deg) {
    int n = blockIdx.x * blockDim.x + threadIdx.x;
    if (n < NN) atomicAdd(&d_hist[deg[n]], 1);
}
__global__ void k_scan() {
    d_suffix[17] = 0;
    for (int dd = 16; dd >= 1; --dd) d_suffix[dd] = d_suffix[dd + 1] + d_hist[dd];
    d_suffix[0] = d_suffix[1];
    for (int dd = 1; dd <= 16; ++dd) d_offset[dd] = d_suffix[dd + 1];
}
__global__ void k_scatter(const int* __restrict__ deg) {
    int n = blockIdx.x * blockDim.x + threadIdx.x;
    if (n < NN) {
        int pos = atomicAdd(&d_offset[deg[n]], 1);
        d_perm[pos] = n;
    }
}

// ---------------- mma + cp.async helpers -------------------------------------
__device__ __forceinline__ void mma_tf32(float& c0, float& c1, float& c2, float& c3,
                                         uint32_t a0, uint32_t a1, uint32_t a2, uint32_t a3,
                                         uint32_t b0, uint32_t b1) {
    asm volatile(
        "mma.sync.aligned.m16n8k8.row.col.f32.tf32.tf32.f32 "
        "{%0,%1,%2,%3}, {%4,%5,%6,%7}, {%8,%9}, {%0,%1,%2,%3};"
        : "+f"(c0), "+f"(c1), "+f"(c2), "+f"(c3)
        : "r"(a0), "r"(a1), "r"(a2), "r"(a3), "r"(b0), "r"(b1));
}
__device__ __forceinline__ void cp_async16(uint32_t dst_smem, const void* src, int src_bytes) {
    asm volatile("cp.async.cg.shared.global [%0], [%1], 16, %2;"
                 :: "r"(dst_smem), "l"(src), "r"(src_bytes));
}
__device__ __forceinline__ void cp_commit() { asm volatile("cp.async.commit_group;"); }
__device__ __forceinline__ void cp_wait0() { asm volatile("cp.async.wait_group 0;"); }
__device__ __forceinline__ void cp_wait1() { asm volatile("cp.async.wait_group 1;"); }

// ---------------- tf32 GEMM: BK=32, cp.async 3-stage pipeline ----------------
// C[M,Nn] = [A|A2][M, K1+K2] @ W[Nn,K]^T (+bias) (relu) (round). A2 optional.
// Inputs pre-rounded to tf32 (rna); loads are raw 16B copies. K1 % 32 == 0.
template<int BM, int BN, int WARPS_M, int WARPS_N, bool RELU, bool ROUND>
__global__ __launch_bounds__(WARPS_M * WARPS_N * 32, (WARPS_M * WARPS_N <= 8) ? 2 : 1)
void tgemm_nt(const float* __restrict__ A, const float* __restrict__ A2, int K1,
              const float* __restrict__ W,
              const float* __restrict__ bias0, const float* __restrict__ bias1,
              float* __restrict__ C, int M, int Nn, int K,
              const int* rowsDev) {
    constexpr int BK = 32;
    constexpr int LDS_ = BK + 4;
    constexpr int STAGES = 3;
    constexpr int WM = BM / WARPS_M;
    constexpr int WN = BN / WARPS_N;
    constexpr int MT = WM / 16;
    constexpr int NTT = WN / 8;
    constexpr int NTHR = WARPS_M * WARPS_N * 32;
    constexpr int AIT = BM * (BK / 4) / NTHR;
    constexpr int BIT = BN * (BK / 4) / NTHR;
    constexpr int ASTRIDE = BM * LDS_;
    constexpr int BSTRIDE = BN * LDS_;

    extern __shared__ uint32_t dynsmem[];
    uint32_t* AsBase = dynsmem;
    uint32_t* BsBase = dynsmem + STAGES * ASTRIDE;
    const uint32_t sbase = (uint32_t)__cvta_generic_to_shared(dynsmem);
    const uint32_t sbaseB = sbase + STAGES * ASTRIDE * 4;

    int rows = rowsDev ? *rowsDev : M;
    int rowBase = blockIdx.y * BM;
    if (rowBase >= rows) return;
    int colBase = blockIdx.x * BN;

    int tid = threadIdx.x;
    int wid = tid >> 5, lane = tid & 31;
    int wm = wid / WARPS_N, wn = wid % WARPS_N;
    int grp = lane >> 2, tg = lane & 3;

    float acc[MT][NTT][4];
#pragma unroll
    for (int i = 0; i < MT; i++)
#pragma unroll
        for (int j = 0; j < NTT; j++) {
            acc[i][j][0] = 0.f; acc[i][j][1] = 0.f; acc[i][j][2] = 0.f; acc[i][j][3] = 0.f;
        }

    const int ar = tid / (BK / 4);
    const int ac4 = (tid % (BK / 4)) * 4;
    constexpr int ARSTEP = NTHR / (BK / 4);
    const int K2 = K - K1;

    auto issue_tile = [&](int k0, int stg) {
        const float* srcA;
        int strA, c0;
        if (A2 && k0 >= K1) { srcA = A2; strA = K2; c0 = k0 - K1; }
        else { srcA = A; strA = K1; c0 = k0; }
#pragma unroll
        for (int u = 0; u < AIT; u++) {
            int r = ar + u * ARSTEP;
            int gr = rowBase + r;
            uint32_t dst = sbase + (uint32_t)(stg * ASTRIDE + r * LDS_ + ac4) * 4;
            cp_async16(dst, &srcA[(size_t)gr * strA + c0 + ac4], (gr < rows) ? 16 : 0);
        }
#pragma unroll
        for (int u = 0; u < BIT; u++) {
            int r = ar + u * ARSTEP;
            uint32_t dst = sbaseB + (uint32_t)(stg * BSTRIDE + r * LDS_ + ac4) * 4;
            cp_async16(dst, &W[(size_t)(colBase + r) * K + k0 + ac4], 16);
        }
        cp_commit();
    };

    issue_tile(0, 0);
    if (BK < K) issue_tile(BK, 1);

    int stage = 0;
    for (int k0 = 0; k0 < K; k0 += BK) {
        if (k0 + BK < K) cp_wait1(); else cp_wait0();
        __syncthreads();
        int kn = k0 + 2 * BK;
        if (kn < K) issue_tile(kn, (stage + 2) % STAGES);

        uint32_t* As = AsBase + stage * ASTRIDE;
        uint32_t* Bs = BsBase + stage * BSTRIDE;
#pragma unroll
        for (int kk = 0; kk < BK; kk += 8) {
            uint32_t af[MT][4];
#pragma unroll
            for (int i = 0; i < MT; i++) {
                int r0 = wm * WM + i * 16 + grp;
                int c = kk + tg;
                af[i][0] = As[r0 * LDS_ + c];
                af[i][1] = As[(r0 + 8) * LDS_ + c];
                af[i][2] = As[r0 * LDS_ + c + 4];
                af[i][3] = As[(r0 + 8) * LDS_ + c + 4];
            }
            uint32_t bf[NTT][2];
#pragma unroll
            for (int j = 0; j < NTT; j++) {
                int n0 = wn * WN + j * 8 + grp;
                bf[j][0] = Bs[n0 * LDS_ + kk + tg];
                bf[j][1] = Bs[n0 * LDS_ + kk + tg + 4];
            }
#pragma unroll
            for (int i = 0; i < MT; i++)
#pragma unroll
                for (int j = 0; j < NTT; j++)
                    mma_tf32(acc[i][j][0], acc[i][j][1], acc[i][j][2], acc[i][j][3],
                             af[i][0], af[i][1], af[i][2], af[i][3], bf[j][0], bf[j][1]);
        }
        stage = (stage + 1) % STAGES;
    }

#pragma unroll
    for (int i = 0; i < MT; i++) {
#pragma unroll
        for (int j = 0; j < NTT; j++) {
            int gc = colBase + wn * WN + j * 8 + 2 * tg;
            float b0v = 0.f, b1v = 0.f;
            if (bias0) { b0v += bias0[gc]; b1v += bias0[gc + 1]; }
            if (bias1) { b0v += bias1[gc]; b1v += bias1[gc + 1]; }
            int gr0 = rowBase + wm * WM + i * 16 + grp;
            if (gr0 < rows) {
                float v0 = acc[i][j][0] + b0v, v1 = acc[i][j][1] + b1v;
                if (RELU) { v0 = fmaxf(v0, 0.f); v1 = fmaxf(v1, 0.f); }
                if (ROUND) { v0 = rtf(v0); v1 = rtf(v1); }
                *(float2*)&C[(size_t)gr0 * Nn + gc] = make_float2(v0, v1);
            }
            int gr1 = gr0 + 8;
            if (gr1 < rows) {
                float v0 = acc[i][j][2] + b0v, v1 = acc[i][j][3] + b1v;
                if (RELU) { v0 = fmaxf(v0, 0.f); v1 = fmaxf(v1, 0.f); }
                if (ROUND) { v0 = rtf(v0); v1 = rtf(v1); }
                *(float2*)&C[(size_t)gr1 * Nn + gc] = make_float2(v0, v1);
            }
        }
    }
}

// ---------------- fast activations (hardware MUFU.TANH) ----------------------
__device__ __forceinline__ float tanh_f(float x) {
    float y;
    asm("tanh.approx.f32 %0, %1;" : "=f"(y) : "f"(x));
    return y;
}
__device__ __forceinline__ float sigm_(float x) {
    return fmaf(tanh_f(0.5f * x), 0.5f, 0.5f);
}

// t = 0 step: gates come straight from G. C full precision; H stored rounded.
template<int H>
__global__ void lstm_step0(const float* __restrict__ G, const int* __restrict__ nbr,
                           float* __restrict__ Hp, float* __restrict__ Cp) {
    constexpr int TPN = H / 4;
    int cnt = d_suffix[1];
    int idx = blockIdx.x * blockDim.x + threadIdx.x;
    int p = idx / TPN;
    if (p >= cnt) return;
    int lane = idx % TPN;
    int node = d_perm[p];
    int nr = nbr[node * DMAXX];
    const float4* gx = (const float4*)&G[(size_t)nr * 4 * H];
    float4 xi = gx[lane], xg = gx[2 * TPN + lane], xo = gx[3 * TPN + lane];
    float4 c, h;
    c.x = sigm_(xi.x) * tanh_f(xg.x); h.x = rtf(sigm_(xo.x) * tanh_f(c.x));
    c.y = sigm_(xi.y) * tanh_f(xg.y); h.y = rtf(sigm_(xo.y) * tanh_f(c.y));
    c.z = sigm_(xi.z) * tanh_f(xg.z); h.z = rtf(sigm_(xo.z) * tanh_f(c.z));
    c.w = sigm_(xi.w) * tanh_f(xg.w); h.w = rtf(sigm_(xo.w) * tanh_f(c.w));
    ((float4*)&Cp[(size_t)p * H])[lane] = c;
    ((float4*)&Hp[(size_t)p * H])[lane] = h;
}

// layer 1: H=128; 32 threads/node. H stored rounded, C full precision.
__global__ void lstm_step1(const int* __restrict__ nbr, int t) {
    int cnt = d_suffix[t + 1];
    int idx = blockIdx.x * blockDim.x + threadIdx.x;
    int p = idx >> 5;
    if (p >= cnt) return;
    int lane = idx & 31;
    int node = d_perm[p];
    int nr = nbr[node * DMAXX + t];
    const float4* gb = (const float4*)&d_GB[(size_t)p * 512];
    const float4* gx = (const float4*)&d_G1[(size_t)nr * 512];
    float4 gi = gb[lane],       xi = gx[lane];
    float4 gf = gb[32 + lane],  xf = gx[32 + lane];
    float4 gg = gb[64 + lane],  xg = gx[64 + lane];
    float4 go = gb[96 + lane],  xo = gx[96 + lane];
    float4* cp = (float4*)&d_C1p[(size_t)p * 128];
    float4* hp = (float4*)&d_H1p[(size_t)p * 128];
    float4 c = cp[lane];
    float4 h;
    c.x = sigm_(gf.x + xf.x) * c.x + sigm_(gi.x + xi.x) * tanh_f(gg.x + xg.x); h.x = rtf(sigm_(go.x + xo.x) * tanh_f(c.x));
    c.y = sigm_(gf.y + xf.y) * c.y + sigm_(gi.y + xi.y) * tanh_f(gg.y + xg.y); h.y = rtf(sigm_(go.y + xo.y) * tanh_f(c.y));
    c.z = sigm_(gf.z + xf.z) * c.z + sigm_(gi.z + xi.z) * tanh_f(gg.z + xg.z); h.z = rtf(sigm_(go.z + xo.z) * tanh_f(c.z));
    c.w = sigm_(gf.w + xf.w) * c.w + sigm_(gi.w + xi.w) * tanh_f(gg.w + xg.w); h.w = rtf(sigm_(go.w + xo.w) * tanh_f(c.w));
    cp[lane] = c; hp[lane] = h;
}

// layer 2: H=256; 64 threads/node
__global__ void lstm_step2(const int* __restrict__ nbr, int t) {
    int cnt = d_suffix[t + 1];
    int idx = blockIdx.x * blockDim.x + threadIdx.x;
    int p = idx >> 6;
    if (p >= cnt) return;
    int lane = idx & 63;
    int node = d_perm[p];
    int nr = nbr[node * DMAXX + t];
    const float4* gb = (const float4*)&d_GB[(size_t)p * 1024];
    const float4* gx = (const float4*)&d_G2[(size_t)nr * 1024];
    float4 gi = gb[lane],        xi = gx[lane];
    float4 gf = gb[64 + lane],   xf = gx[64 + lane];
    float4 gg = gb[128 + lane],  xg = gx[128 + lane];
    float4 go = gb[192 + lane],  xo = gx[192 + lane];
    float4* cp = (float4*)&d_C2p[(size_t)p * 256];
    float4* hp = (float4*)&d_H2p[(size_t)p * 256];
    float4 c = cp[lane];
    float4 h;
    c.x = sigm_(gf.x + xf.x) * c.x + sigm_(gi.x + xi.x) * tanh_f(gg.x + xg.x); h.x = rtf(sigm_(go.x + xo.x) * tanh_f(c.x));
    c.y = sigm_(gf.y + xf.y) * c.y + sigm_(gi.y + xi.y) * tanh_f(gg.y + xg.y); h.y = rtf(sigm_(go.y + xo.y) * tanh_f(c.y));
    c.z = sigm_(gf.z + xf.z) * c.z + sigm_(gi.z + xi.z) * tanh_f(gg.z + xg.z); h.z = rtf(sigm_(go.z + xo.z) * tanh_f(c.z));
    c.w = sigm_(gf.w + xf.w) * c.w + sigm_(gi.w + xi.w) * tanh_f(gg.w + xg.w); h.w = rtf(sigm_(go.w + xo.w) * tanh_f(c.w));
    cp[lane] = c; hp[lane] = h;
}

// scatter permuted final hidden state back to natural node order
__global__ void k_scatter_h1() {
    int idx = blockIdx.x * blockDim.x + threadIdx.x;
    if (idx >= NN * 32) return;
    int p = idx >> 5, lane = idx & 31;
    int node = d_perm[p];
    ((float4*)d_M1)[node * 32 + lane] = ((const float4*)d_H1p)[p * 32 + lane];
}
__global__ void k_scatter_h2() {
    int idx = blockIdx.x * blockDim.x + threadIdx.x;
    if (idx >= NN * 64) return;
    int p = idx >> 6, lane = idx & 63;
    int node = d_perm[p];
    ((float4*)d_M2)[node * 64 + lane] = ((const float4*)d_H2p)[p * 64 + lane];
}

// ---------------- launch -----------------------------------------------------
extern "C" void kernel_launch(void* const* d_in, const int* in_sizes, int n_in,
                              void* d_out, int out_size) {
    const float* feat    = (const float*)d_in[0];
    const int*   nbr     = (const int*)  d_in[1];
    const int*   deg     = (const int*)  d_in[2];
    const float* Wih1    = (const float*)d_in[3];
    const float* Whh1    = (const float*)d_in[4];
    const float* bih1    = (const float*)d_in[5];
    const float* bhh1    = (const float*)d_in[6];
    const float* Wself1  = (const float*)d_in[7];
    const float* Wneigh1 = (const float*)d_in[8];
    const float* b1      = (const float*)d_in[9];
    const float* Wih2    = (const float*)d_in[10];
    const float* Whh2    = (const float*)d_in[11];
    const float* bih2    = (const float*)d_in[12];
    const float* bhh2    = (const float*)d_in[13];
    const float* Wself2  = (const float*)d_in[14];
    const float* Wneigh2 = (const float*)d_in[15];
    const float* b2      = (const float*)d_in[16];
    float* out = (float*)d_out;

    float *pG1, *pGB, *pH1, *pC1, *pM1, *pX1, *pG2, *pH2, *pC2, *pM2, *pFr;
    float *pWih1r, *pWhh1r, *pWih2r, *pWhh2r, *pWfc1, *pWfc2;
    int* pSuf;
    cudaGetSymbolAddress((void**)&pG1, d_G1);
    cudaGetSymbolAddress((void**)&pGB, d_GB);
    cudaGetSymbolAddress((void**)&pH1, d_H1p);
    cudaGetSymbolAddress((void**)&pC1, d_C1p);
    cudaGetSymbolAddress((void**)&pM1, d_M1);
    cudaGetSymbolAddress((void**)&pX1, d_X1);
    cudaGetSymbolAddress((void**)&pG2, d_G2);
    cudaGetSymbolAddress((void**)&pH2, d_H2p);
    cudaGetSymbolAddress((void**)&pC2, d_C2p);
    cudaGetSymbolAddress((void**)&pM2, d_M2);
    cudaGetSymbolAddress((void**)&pFr, d_Fr);
    cudaGetSymbolAddress((void**)&pWih1r, d_Wih1r);
    cudaGetSymbolAddress((void**)&pWhh1r, d_Whh1r);
    cudaGetSymbolAddress((void**)&pWih2r, d_Wih2r);
    cudaGetSymbolAddress((void**)&pWhh2r, d_Whh2r);
    cudaGetSymbolAddress((void**)&pWfc1, d_Wfc1);
    cudaGetSymbolAddress((void**)&pWfc2, d_Wfc2);
    cudaGetSymbolAddress((void**)&pSuf, d_suffix);

    const int SM_WIDE = 3 * (128 + 256) * 36 * 4;   // 165888
    const int SM_SMALL = 3 * (128 + 64) * 36 * 4;   // 82944
    cudaFuncSetAttribute((const void*)tgemm_nt<128, 256, 2, 8, false, false>,
                         cudaFuncAttributeMaxDynamicSharedMemorySize, SM_WIDE);
    cudaFuncSetAttribute((const void*)tgemm_nt<128, 256, 2, 8, true, true>,
                         cudaFuncAttributeMaxDynamicSharedMemorySize, SM_WIDE);
    cudaFuncSetAttribute((const void*)tgemm_nt<128, 64, 2, 4, false, false>,
                         cudaFuncAttributeMaxDynamicSharedMemorySize, SM_SMALL);

    const int MB = (NN + 127) / 128;   // 235

    k_round_all<<<(R_WHH2 + 255) / 256, 256>>>(feat, Wih1, Whh1, Wih2, Whh2);
    k_pack2<<<(256 * 256 / 4 + 255) / 256, 256>>>(Wself1, Wneigh1, pWfc1, 256, 128, 128);
    k_pack2<<<(64 * 512 / 4 + 255) / 256, 256>>>(Wself2, Wneigh2, pWfc2, 64, 256, 256);

    k_hist_zero<<<1, 32>>>();
    k_hist<<<(NN + 255) / 256, 256>>>(deg);
    k_scan<<<1, 1>>>();
    k_scatter<<<(NN + 255) / 256, 256>>>(deg);

    // ---------------- layer 1 ----------------
    tgemm_nt<128, 256, 2, 8, false, false><<<dim3(2, MB), 512, SM_WIDE>>>(
        pFr, nullptr, 128, pWih1r, bih1, bhh1, pG1, NN, 512, 128, nullptr);
    lstm_step0<128><<<(NN * 32 + 255) / 256, 256>>>(pG1, nbr, pH1, pC1);
    for (int t = 1; t < DMAXX; t++) {
        tgemm_nt<128, 256, 2, 8, false, false><<<dim3(2, MB), 512, SM_WIDE>>>(
            pH1, nullptr, 128, pWhh1r, nullptr, nullptr, pGB, NN, 512, 128, pSuf + (t + 1));
        lstm_step1<<<(NN * 32 + 255) / 256, 256>>>(nbr, t);
    }
    k_scatter_h1<<<(NN * 32 + 255) / 256, 256>>>();
    // X1 = relu([feat|M1] @ Wfc1^T + b1), rounded (merged FC, single 256-col tile)
    tgemm_nt<128, 256, 2, 8, true, true><<<dim3(1, MB), 512, SM_WIDE>>>(
        pFr, pM1, 128, pWfc1, b1, nullptr, pX1, NN, 256, 256, nullptr);

    // ---------------- layer 2 ----------------
    tgemm_nt<128, 256, 2, 8, false, false><<<dim3(4, MB), 512, SM_WIDE>>>(
        pX1, nullptr, 256, pWih2r, bih2, bhh2, pG2, NN, 1024, 256, nullptr);
    lstm_step0<256><<<(NN * 64 + 255) / 256, 256>>>(pG2, nbr, pH2, pC2);
    for (int t = 1; t < DMAXX; t++) {
        tgemm_nt<128, 256, 2, 8, false, false><<<dim3(4, MB), 512, SM_WIDE>>>(
            pH2, nullptr, 256, pWhh2r, nullptr, nullptr, pGB, NN, 1024, 256, pSuf + (t + 1));
        lstm_step2<<<(NN * 64 + 255) / 256, 256>>>(nbr, t);
    }
    k_scatter_h2<<<(NN * 64 + 255) / 256, 256>>>();
    // out = [X1|M2] @ Wfc2^T + b2
    tgemm_nt<128, 64, 2, 4, false, false><<<dim3(1, MB), 256, SM_SMALL>>>(
        pX1, pM2, 256, pWfc2, b2, nullptr, out, NN, 64, 512, nullptr);
}

// round 16
// speedup vs baseline: 2.0581x; 2.0581x over previous
#include <cuda_runtime.h>
#include <cuda_fp16.h>
#include <cstdint>

#define NN 30000
#define DMAXX 16

// ---------------- scratch (static device arrays; no cudaMalloc) -------------
__device__ __align__(16) float  d_G1[(size_t)NN * 512];      // gate precompute L1 (f32)
__device__ __align__(16) float  d_GB[(size_t)NN * 1024];     // recurrent gate buffer (f32)
__device__ __align__(16) float  d_G2[(size_t)NN * 1024];     // gate precompute L2 (f32)
__device__ __align__(16) float  d_C1p[(size_t)NN * 128];     // C state (f32)
__device__ __align__(16) float  d_C2p[(size_t)NN * 256];
__device__ __align__(16) __half d_H1p[(size_t)NN * 128];     // H state (fp16)
__device__ __align__(16) __half d_H2p[(size_t)NN * 256];
__device__ __align__(16) __half d_M1[(size_t)NN * 128];      // aggregated neighbor hidden
__device__ __align__(16) __half d_M2[(size_t)NN * 256];
__device__ __align__(16) __half d_X1[(size_t)NN * 256];      // layer-1 output
__device__ __align__(16) __half d_Frh[(size_t)NN * 128];     // feat fp16
__device__ __align__(16) __half d_Wih1h[512 * 128];
__device__ __align__(16) __half d_Whh1h[512 * 128];
__device__ __align__(16) __half d_Wih2h[1024 * 256];
__device__ __align__(16) __half d_Whh2h[1024 * 256];
__device__ __align__(16) __half d_Wfc1h[256 * 256];          // [Wself1|Wneigh1]
__device__ __align__(16) __half d_Wfc2h[64 * 512];           // [Wself2|Wneigh2]
__device__ int d_perm[NN];
__device__ int d_hist[17];
__device__ int d_suffix[18];
__device__ int d_offset[17];

// ---------------- fp16 conversion helpers ------------------------------------
__device__ __forceinline__ uint2 f4_to_h4(float4 v) {
    __half2 lo = __floats2half2_rn(v.x, v.y);
    __half2 hi = __floats2half2_rn(v.z, v.w);
    uint2 r;
    r.x = *(uint32_t*)&lo;
    r.y = *(uint32_t*)&hi;
    return r;
}

#define R_FEAT 960000
#define R_WIH1 (R_FEAT + 16384)
#define R_WHH1 (R_WIH1 + 16384)
#define R_WIH2 (R_WHH1 + 65536)
#define R_WHH2 (R_WIH2 + 65536)
__global__ void k_half_all(const float* __restrict__ feat,
                           const float* __restrict__ wih1, const float* __restrict__ whh1,
                           const float* __restrict__ wih2, const float* __restrict__ whh2) {
    int i = blockIdx.x * blockDim.x + threadIdx.x;
    if (i < R_FEAT)      ((uint2*)d_Frh)[i]            = f4_to_h4(((const float4*)feat)[i]);
    else if (i < R_WIH1) ((uint2*)d_Wih1h)[i - R_FEAT] = f4_to_h4(((const float4*)wih1)[i - R_FEAT]);
    else if (i < R_WHH1) ((uint2*)d_Whh1h)[i - R_WIH1] = f4_to_h4(((const float4*)whh1)[i - R_WIH1]);
    else if (i < R_WIH2) ((uint2*)d_Wih2h)[i - R_WHH1] = f4_to_h4(((const float4*)wih2)[i - R_WHH1]);
    else if (i < R_WHH2) ((uint2*)d_Whh2h)[i - R_WIH2] = f4_to_h4(((const float4*)whh2)[i - R_WIH2]);
}

__global__ void k_pack2h(const float* __restrict__ a, const float* __restrict__ b,
                         __half* __restrict__ out, int rows, int k1, int k2) {
    int ktot = k1 + k2;
    int n4 = rows * ktot / 4;
    int i = blockIdx.x * blockDim.x + threadIdx.x;
    if (i >= n4) return;
    int r = i / (ktot / 4), c4 = (i % (ktot / 4)) * 4;
    float4 v = (c4 < k1) ? *(const float4*)&a[(size_t)r * k1 + c4]
                         : *(const float4*)&b[(size_t)r * k2 + (c4 - k1)];
    ((uint2*)out)[i] = f4_to_h4(v);
}

// ---------------- degree counting sort (descending) -------------------------
__global__ void k_hist_zero() { if (threadIdx.x < 17) d_hist[threadIdx.x] = 0; }
__global__ void k_hist(const int* __restrict__ deg) {
    int n = blockIdx.x * blockDim.x + threadIdx.x;
    if (n < NN) atomicAdd(&d_hist[deg[n]], 1);
}
__global__ void k_scan() {
    d_suffix[17] = 0;
    for (int dd = 16; dd >= 1; --dd) d_suffix[dd] = d_suffix[dd + 1] + d_hist[dd];
    d_suffix[0] = d_suffix[1];
    for (int dd = 1; dd <= 16; ++dd) d_offset[dd] = d_suffix[dd + 1];
}
__global__ void k_scatter(const int* __restrict__ deg) {
    int n = blockIdx.x * blockDim.x + threadIdx.x;
    if (n < NN) {
        int pos = atomicAdd(&d_offset[deg[n]], 1);
        d_perm[pos] = n;
    }
}

// ---------------- mma + cp.async helpers -------------------------------------
__device__ __forceinline__ void mma_f16(float& c0, float& c1, float& c2, float& c3,
                                        uint32_t a0, uint32_t a1, uint32_t a2, uint32_t a3,
                                        uint32_t b0, uint32_t b1) {
    asm volatile(
        "mma.sync.aligned.m16n8k16.row.col.f32.f16.f16.f32 "
        "{%0,%1,%2,%3}, {%4,%5,%6,%7}, {%8,%9}, {%0,%1,%2,%3};"
        : "+f"(c0), "+f"(c1), "+f"(c2), "+f"(c3)
        : "r"(a0), "r"(a1), "r"(a2), "r"(a3), "r"(b0), "r"(b1));
}
__device__ __forceinline__ void cp_async16(uint32_t dst_smem, const void* src, int src_bytes) {
    asm volatile("cp.async.cg.shared.global [%0], [%1], 16, %2;"
                 :: "r"(dst_smem), "l"(src), "r"(src_bytes));
}
__device__ __forceinline__ void cp_commit() { asm volatile("cp.async.commit_group;"); }
__device__ __forceinline__ void cp_wait0() { asm volatile("cp.async.wait_group 0;"); }
__device__ __forceinline__ void cp_wait1() { asm volatile("cp.async.wait_group 1;"); }

// ---------------- fp16 GEMM: BK=32, cp.async 3-stage pipeline ----------------
// C[M,Nn] = [A|A2][M, K1+K2] @ W[Nn,K]^T (+bias0+bias1) (relu).
// A/A2/W fp16 (pre-rounded rn), f32 accumulate. HALFOUT: write __half2, else float2.
// smem rows padded to LDSH=40 halves -> 32-bit fragment LDS conflict-free.
template<int BM, int BN, int WARPS_M, int WARPS_N, bool RELU, bool HALFOUT>
__global__ __launch_bounds__(256, 2)
void tgemm_h(const __half* __restrict__ A, const __half* __restrict__ A2, int K1,
             const __half* __restrict__ W,
             const float* __restrict__ bias0, const float* __restrict__ bias1,
             void* __restrict__ Cv, int M, int Nn, int K,
             const int* rowsDev) {
    constexpr int BK = 32;                 // halves per tile row
    constexpr int LDSH = 40;               // padded halves per row
    constexpr int STAGES = 3;
    constexpr int WM = BM / WARPS_M;
    constexpr int WN = BN / WARPS_N;
    constexpr int MT = WM / 16;
    constexpr int NTT = WN / 8;
    constexpr int NTHR = WARPS_M * WARPS_N * 32;
    constexpr int AIT = BM * 4 / NTHR;     // 16B chunks per thread (A): BK/8=4 per row
    constexpr int BIT = BN * 4 / NTHR;
    constexpr int ASTRIDE = BM * LDSH;     // halves
    constexpr int BSTRIDE = BN * LDSH;

    extern __shared__ uint16_t hsm[];
    uint16_t* AsBase = hsm;
    uint16_t* BsBase = hsm + STAGES * ASTRIDE;
    const uint32_t sbase = (uint32_t)__cvta_generic_to_shared(hsm);
    const uint32_t sbaseB = sbase + STAGES * ASTRIDE * 2;

    int rows = rowsDev ? *rowsDev : M;
    int rowBase = blockIdx.y * BM;
    if (rowBase >= rows) return;
    int colBase = blockIdx.x * BN;

    int tid = threadIdx.x;
    int wid = tid >> 5, lane = tid & 31;
    int wm = wid / WARPS_N, wn = wid % WARPS_N;
    int grp = lane >> 2, tg = lane & 3;

    float acc[MT][NTT][4];
#pragma unroll
    for (int i = 0; i < MT; i++)
#pragma unroll
        for (int j = 0; j < NTT; j++) {
            acc[i][j][0] = 0.f; acc[i][j][1] = 0.f; acc[i][j][2] = 0.f; acc[i][j][3] = 0.f;
        }

    const int ar = tid >> 2;               // row handled (4 threads/row)
    const int ac8 = (tid & 3) * 8;         // half offset within row
    constexpr int ARSTEP = NTHR / 4;       // 64
    const int K2 = K - K1;

    auto issue_tile = [&](int k0, int stg) {
        const __half* srcA;
        int strA, c0;
        if (A2 && k0 >= K1) { srcA = A2; strA = K2; c0 = k0 - K1; }
        else { srcA = A; strA = K1; c0 = k0; }
#pragma unroll
        for (int u = 0; u < AIT; u++) {
            int r = ar + u * ARSTEP;
            int gr = rowBase + r;
            uint32_t dst = sbase + (uint32_t)(stg * ASTRIDE + r * LDSH + ac8) * 2;
            cp_async16(dst, &srcA[(size_t)gr * strA + c0 + ac8], (gr < rows) ? 16 : 0);
        }
#pragma unroll
        for (int u = 0; u < BIT; u++) {
            int r = ar + u * ARSTEP;
            uint32_t dst = sbaseB + (uint32_t)(stg * BSTRIDE + r * LDSH + ac8) * 2;
            cp_async16(dst, &W[(size_t)(colBase + r) * K + k0 + ac8], 16);
        }
        cp_commit();
    };

    issue_tile(0, 0);
    if (BK < K) issue_tile(BK, 1);

    int stage = 0;
    for (int k0 = 0; k0 < K; k0 += BK) {
        if (k0 + BK < K) cp_wait1(); else cp_wait0();
        __syncthreads();
        int kn = k0 + 2 * BK;
        if (kn < K) issue_tile(kn, (stage + 2) % STAGES);

        const uint16_t* As = AsBase + stage * ASTRIDE;
        const uint16_t* Bs = BsBase + stage * BSTRIDE;
#pragma unroll
        for (int kk = 0; kk < BK; kk += 16) {
            uint32_t af[MT][4];
#pragma unroll
            for (int i = 0; i < MT; i++) {
                int r0 = wm * WM + i * 16 + grp;
                int c = kk + 2 * tg;
                af[i][0] = *(const uint32_t*)&As[r0 * LDSH + c];
                af[i][1] = *(const uint32_t*)&As[(r0 + 8) * LDSH + c];
                af[i][2] = *(const uint32_t*)&As[r0 * LDSH + c + 8];
                af[i][3] = *(const uint32_t*)&As[(r0 + 8) * LDSH + c + 8];
            }
            uint32_t bf[NTT][2];
#pragma unroll
            for (int j = 0; j < NTT; j++) {
                int n0 = wn * WN + j * 8 + grp;
                bf[j][0] = *(const uint32_t*)&Bs[n0 * LDSH + kk + 2 * tg];
                bf[j][1] = *(const uint32_t*)&Bs[n0 * LDSH + kk + 2 * tg + 8];
            }
#pragma unroll
            for (int i = 0; i < MT; i++)
#pragma unroll
                for (int j = 0; j < NTT; j++)
                    mma_f16(acc[i][j][0], acc[i][j][1], acc[i][j][2], acc[i][j][3],
                            af[i][0], af[i][1], af[i][2], af[i][3], bf[j][0], bf[j][1]);
        }
        stage = (stage + 1) % STAGES;
    }

#pragma unroll
    for (int i = 0; i < MT; i++) {
#pragma unroll
        for (int j = 0; j < NTT; j++) {
            int gc = colBase + wn * WN + j * 8 + 2 * tg;
            float b0v = 0.f, b1v = 0.f;
            if (bias0) { b0v += bias0[gc]; b1v += bias0[gc + 1]; }
            if (bias1) { b0v += bias1[gc]; b1v += bias1[gc + 1]; }
#pragma unroll
            for (int h = 0; h < 2; h++) {
                int gr = rowBase + wm * WM + i * 16 + grp + h * 8;
                if (gr < rows) {
                    float v0 = acc[i][j][2 * h] + b0v, v1 = acc[i][j][2 * h + 1] + b1v;
                    if (RELU) { v0 = fmaxf(v0, 0.f); v1 = fmaxf(v1, 0.f); }
                    if (HALFOUT) {
                        *(__half2*)((__half*)Cv + (size_t)gr * Nn + gc) = __floats2half2_rn(v0, v1);
                    } else {
                        *(float2*)((float*)Cv + (size_t)gr * Nn + gc) = make_float2(v0, v1);
                    }
                }
            }
        }
    }
}

// ---------------- fast activations (hardware MUFU.TANH) ----------------------
__device__ __forceinline__ float tanh_f(float x) {
    float y;
    asm("tanh.approx.f32 %0, %1;" : "=f"(y) : "f"(x));
    return y;
}
__device__ __forceinline__ float sigm_(float x) {
    return fmaf(tanh_f(0.5f * x), 0.5f, 0.5f);
}
__device__ __forceinline__ uint2 pack_h4(float a, float b, float c, float d) {
    __half2 lo = __floats2half2_rn(a, b);
    __half2 hi = __floats2half2_rn(c, d);
    uint2 r;
    r.x = *(uint32_t*)&lo;
    r.y = *(uint32_t*)&hi;
    return r;
}

// t = 0 step: gates come straight from G. C f32; H stored fp16.
template<int H>
__global__ void lstm_step0(const float* __restrict__ G, const int* __restrict__ nbr,
                           __half* __restrict__ Hp, float* __restrict__ Cp) {
    constexpr int TPN = H / 4;
    int cnt = d_suffix[1];
    int idx = blockIdx.x * blockDim.x + threadIdx.x;
    int p = idx / TPN;
    if (p >= cnt) return;
    int lane = idx % TPN;
    int node = d_perm[p];
    int nr = nbr[node * DMAXX];
    const float4* gx = (const float4*)&G[(size_t)nr * 4 * H];
    float4 xi = gx[lane], xg = gx[2 * TPN + lane], xo = gx[3 * TPN + lane];
    float4 c, h;
    c.x = sigm_(xi.x) * tanh_f(xg.x); h.x = sigm_(xo.x) * tanh_f(c.x);
    c.y = sigm_(xi.y) * tanh_f(xg.y); h.y = sigm_(xo.y) * tanh_f(c.y);
    c.z = sigm_(xi.z) * tanh_f(xg.z); h.z = sigm_(xo.z) * tanh_f(c.z);
    c.w = sigm_(xi.w) * tanh_f(xg.w); h.w = sigm_(xo.w) * tanh_f(c.w);
    ((float4*)&Cp[(size_t)p * H])[lane] = c;
    ((uint2*)&Hp[(size_t)p * H])[lane] = pack_h4(h.x, h.y, h.z, h.w);
}

// layer 1: H=128; 32 threads/node
__global__ void lstm_step1(const int* __restrict__ nbr, int t) {
    int cnt = d_suffix[t + 1];
    int idx = blockIdx.x * blockDim.x + threadIdx.x;
    int p = idx >> 5;
    if (p >= cnt) return;
    int lane = idx & 31;
    int node = d_perm[p];
    int nr = nbr[node * DMAXX + t];
    const float4* gb = (const float4*)&d_GB[(size_t)p * 512];
    const float4* gx = (const float4*)&d_G1[(size_t)nr * 512];
    float4 gi = gb[lane],       xi = gx[lane];
    float4 gf = gb[32 + lane],  xf = gx[32 + lane];
    float4 gg = gb[64 + lane],  xg = gx[64 + lane];
    float4 go = gb[96 + lane],  xo = gx[96 + lane];
    float4* cp = (float4*)&d_C1p[(size_t)p * 128];
    float4 c = cp[lane];
    float4 h;
    c.x = sigm_(gf.x + xf.x) * c.x + sigm_(gi.x + xi.x) * tanh_f(gg.x + xg.x); h.x = sigm_(go.x + xo.x) * tanh_f(c.x);
    c.y = sigm_(gf.y + xf.y) * c.y + sigm_(gi.y + xi.y) * tanh_f(gg.y + xg.y); h.y = sigm_(go.y + xo.y) * tanh_f(c.y);
    c.z = sigm_(gf.z + xf.z) * c.z + sigm_(gi.z + xi.z) * tanh_f(gg.z + xg.z); h.z = sigm_(go.z + xo.z) * tanh_f(c.z);
    c.w = sigm_(gf.w + xf.w) * c.w + sigm_(gi.w + xi.w) * tanh_f(gg.w + xg.w); h.w = sigm_(go.w + xo.w) * tanh_f(c.w);
    cp[lane] = c;
    ((uint2*)&d_H1p[(size_t)p * 128])[lane] = pack_h4(h.x, h.y, h.z, h.w);
}

// layer 2: H=256; 64 threads/node
__global__ void lstm_step2(const int* __restrict__ nbr, int t) {
    int cnt = d_suffix[t + 1];
    int idx = blockIdx.x * blockDim.x + threadIdx.x;
    int p = idx >> 6;
    if (p >= cnt) return;
    int lane = idx & 63;
    int node = d_perm[p];
    int nr = nbr[node * DMAXX + t];
    const float4* gb = (const float4*)&d_GB[(size_t)p * 1024];
    const float4* gx = (const float4*)&d_G2[(size_t)nr * 1024];
    float4 gi = gb[lane],        xi = gx[lane];
    float4 gf = gb[64 + lane],   xf = gx[64 + lane];
    float4 gg = gb[128 + lane],  xg = gx[128 + lane];
    float4 go = gb[192 + lane],  xo = gx[192 + lane];
    float4* cp = (float4*)&d_C2p[(size_t)p * 256];
    float4 c = cp[lane];
    float4 h;
    c.x = sigm_(gf.x + xf.x) * c.x + sigm_(gi.x + xi.x) * tanh_f(gg.x + xg.x); h.x = sigm_(go.x + xo.x) * tanh_f(c.x);
    c.y = sigm_(gf.y + xf.y) * c.y + sigm_(gi.y + xi.y) * tanh_f(gg.y + xg.y); h.y = sigm_(go.y + xo.y) * tanh_f(c.y);
    c.z = sigm_(gf.z + xf.z) * c.z + sigm_(gi.z + xi.z) * tanh_f(gg.z + xg.z); h.z = sigm_(go.z + xo.z) * tanh_f(c.z);
    c.w = sigm_(gf.w + xf.w) * c.w + sigm_(gi.w + xi.w) * tanh_f(gg.w + xg.w); h.w = sigm_(go.w + xo.w) * tanh_f(c.w);
    cp[lane] = c;
    ((uint2*)&d_H2p[(size_t)p * 256])[lane] = pack_h4(h.x, h.y, h.z, h.w);
}

// scatter permuted final hidden (fp16) back to natural node order
__global__ void k_scatter_h1() {
    int idx = blockIdx.x * blockDim.x + threadIdx.x;
    if (idx >= NN * 32) return;
    int p = idx >> 5, lane = idx & 31;
    int node = d_perm[p];
    ((uint2*)d_M1)[node * 32 + lane] = ((const uint2*)d_H1p)[p * 32 + lane];
}
__global__ void k_scatter_h2() {
    int idx = blockIdx.x * blockDim.x + threadIdx.x;
    if (idx >= NN * 64) return;
    int p = idx >> 6, lane = idx & 63;
    int node = d_perm[p];
    ((uint2*)d_M2)[node * 64 + lane] = ((const uint2*)d_H2p)[p * 64 + lane];
}

// ---------------- launch -----------------------------------------------------
extern "C" void kernel_launch(void* const* d_in, const int* in_sizes, int n_in,
                              void* d_out, int out_size) {
    const float* feat    = (const float*)d_in[0];
    const int*   nbr     = (const int*)  d_in[1];
    const int*   deg     = (const int*)  d_in[2];
    const float* Wih1    = (const float*)d_in[3];
    const float* Whh1    = (const float*)d_in[4];
    const float* bih1    = (const float*)d_in[5];
    const float* bhh1    = (const float*)d_in[6];
    const float* Wself1  = (const float*)d_in[7];
    const float* Wneigh1 = (const float*)d_in[8];
    const float* b1      = (const float*)d_in[9];
    const float* Wih2    = (const float*)d_in[10];
    const float* Whh2    = (const float*)d_in[11];
    const float* bih2    = (const float*)d_in[12];
    const float* bhh2    = (const float*)d_in[13];
    const float* Wself2  = (const float*)d_in[14];
    const float* Wneigh2 = (const float*)d_in[15];
    const float* b2      = (const float*)d_in[16];
    float* out = (float*)d_out;

    float *pG1, *pGB, *pG2, *pC1, *pC2;
    __half *pH1, *pH2, *pM1, *pM2, *pX1, *pFrh;
    __half *pWih1h, *pWhh1h, *pWih2h, *pWhh2h, *pWfc1h, *pWfc2h;
    int* pSuf;
    cudaGetSymbolAddress((void**)&pG1, d_G1);
    cudaGetSymbolAddress((void**)&pGB, d_GB);
    cudaGetSymbolAddress((void**)&pG2, d_G2);
    cudaGetSymbolAddress((void**)&pC1, d_C1p);
    cudaGetSymbolAddress((void**)&pC2, d_C2p);
    cudaGetSymbolAddress((void**)&pH1, d_H1p);
    cudaGetSymbolAddress((void**)&pH2, d_H2p);
    cudaGetSymbolAddress((void**)&pM1, d_M1);
    cudaGetSymbolAddress((void**)&pM2, d_M2);
    cudaGetSymbolAddress((void**)&pX1, d_X1);
    cudaGetSymbolAddress((void**)&pFrh, d_Frh);
    cudaGetSymbolAddress((void**)&pWih1h, d_Wih1h);
    cudaGetSymbolAddress((void**)&pWhh1h, d_Whh1h);
    cudaGetSymbolAddress((void**)&pWih2h, d_Wih2h);
    cudaGetSymbolAddress((void**)&pWhh2h, d_Whh2h);
    cudaGetSymbolAddress((void**)&pWfc1h, d_Wfc1h);
    cudaGetSymbolAddress((void**)&pWfc2h, d_Wfc2h);
    cudaGetSymbolAddress((void**)&pSuf, d_suffix);

    const int SM_BIG = 3 * (128 + 128) * 40 * 2;    // 61440
    const int SM_SMALL = 3 * (128 + 64) * 40 * 2;   // 46080
    cudaFuncSetAttribute((const void*)tgemm_h<128, 128, 2, 4, false, false>,
                         cudaFuncAttributeMaxDynamicSharedMemorySize, SM_BIG);
    cudaFuncSetAttribute((const void*)tgemm_h<128, 128, 2, 4, true, true>,
                         cudaFuncAttributeMaxDynamicSharedMemorySize, SM_BIG);
    cudaFuncSetAttribute((const void*)tgemm_h<128, 64, 2, 4, false, false>,
                         cudaFuncAttributeMaxDynamicSharedMemorySize, SM_SMALL);

    const int MB = (NN + 127) / 128;   // 235

    k_half_all<<<(R_WHH2 + 255) / 256, 256>>>(feat, Wih1, Whh1, Wih2, Whh2);
    k_pack2h<<<(256 * 256 / 4 + 255) / 256, 256>>>(Wself1, Wneigh1, pWfc1h, 256, 128, 128);
    k_pack2h<<<(64 * 512 / 4 + 255) / 256, 256>>>(Wself2, Wneigh2, pWfc2h, 64, 256, 256);

    k_hist_zero<<<1, 32>>>();
    k_hist<<<(NN + 255) / 256, 256>>>(deg);
    k_scan<<<1, 1>>>();
    k_scatter<<<(NN + 255) / 256, 256>>>(deg);

    // ---------------- layer 1 ----------------
    tgemm_h<128, 128, 2, 4, false, false><<<dim3(4, MB), 256, SM_BIG>>>(
        pFrh, nullptr, 128, pWih1h, bih1, bhh1, pG1, NN, 512, 128, nullptr);
    lstm_step0<128><<<(NN * 32 + 255) / 256, 256>>>(pG1, nbr, pH1, pC1);
    for (int t = 1; t < DMAXX; t++) {
        tgemm_h<128, 128, 2, 4, false, false><<<dim3(4, MB), 256, SM_BIG>>>(
            pH1, nullptr, 128, pWhh1h, nullptr, nullptr, pGB, NN, 512, 128, pSuf + (t + 1));
        lstm_step1<<<(NN * 32 + 255) / 256, 256>>>(nbr, t);
    }
    k_scatter_h1<<<(NN * 32 + 255) / 256, 256>>>();
    // X1 = relu([feat|M1] @ Wfc1^T + b1) -> fp16
    tgemm_h<128, 128, 2, 4, true, true><<<dim3(2, MB), 256, SM_BIG>>>(
        pFrh, pM1, 128, pWfc1h, b1, nullptr, pX1, NN, 256, 256, nullptr);

    // ---------------- layer 2 ----------------
    tgemm_h<128, 128, 2, 4, false, false><<<dim3(8, MB), 256, SM_BIG>>>(
        pX1, nullptr, 256, pWih2h, bih2, bhh2, pG2, NN, 1024, 256, nullptr);
    lstm_step0<256><<<(NN * 64 + 255) / 256, 256>>>(pG2, nbr, pH2, pC2);
    for (int t = 1; t < DMAXX; t++) {
        tgemm_h<128, 128, 2, 4, false, false><<<dim3(8, MB), 256, SM_BIG>>>(
            pH2, nullptr, 256, pWhh2h, nullptr, nullptr, pGB, NN, 1024, 256, pSuf + (t + 1));
        lstm_step2<<<(NN * 64 + 255) / 256, 256>>>(nbr, t);
    }
    k_scatter_h2<<<(NN * 64 + 255) / 256, 256>>>();
    // out = [X1|M2] @ Wfc2^T + b2 (float out)
    tgemm_h<128, 64, 2, 4, false, false><<<dim3(1, MB), 256, SM_SMALL>>>(
        pX1, pM2, 256, pWfc2h, b2, nullptr, out, NN, 64, 512, nullptr);
}